// round 7
// baseline (speedup 1.0000x reference)
#include <cuda_runtime.h>
#include <cuda_fp16.h>
#include <cstdint>

// GraphConv, 2-launch pipeline:
//  K1 prep (fused):
//    blocks [0, META_BLOCKS):       eidx/meta precompute + pf sentinel zero
//    blocks [META_BLOCKS, +1024):   pf = fp16(feats @ Wf^T) via HMMA
//  K2 gather: out = relu( inv*( sum pf[eidx_n] + srel.W_rel ) + b )
// Shapes fixed: B=8, P=K=16384, N=16, IN=64, REL=3, OUT=64.

#define LOG2_K 14
#define ROWS_TOTAL (8 * 16384)
#define ZROW ROWS_TOTAL

#define META_BLOCKS 2048
#define META_ROWS_PER_BLOCK 64   // 4 iterations x 16 rows
#define PROJ_BLOCKS (ROWS_TOTAL / 128)

__device__ __align__(16) __half g_pf[((size_t)ROWS_TOTAL + 1) * 64];
__device__ __align__(16) int    g_eidx[(size_t)ROWS_TOTAL * 16];
__device__ __align__(16) float4 g_meta[ROWS_TOTAL];

__device__ __forceinline__ uint32_t smem_u32(const void* p) {
    uint32_t a;
    asm("{ .reg .u64 t; cvta.to.shared.u64 t, %1; cvt.u32.u64 %0, t; }"
        : "=r"(a) : "l"(p));
    return a;
}

// ---------------------------------------------------------------------------
// Kernel 1: fused meta + proj.
// ---------------------------------------------------------------------------
#define A_STRIDE 72
#define W_STRIDE 66

__global__ __launch_bounds__(256)
void prep_kernel(const float* __restrict__ feats,
                 const float* __restrict__ W,      // [64][67]
                 const int*   __restrict__ n_idxs,
                 const int*   __restrict__ nvalid,
                 const float* __restrict__ nrel,
                 __half*      __restrict__ pf,
                 int*         __restrict__ eidx,
                 float4*      __restrict__ meta,
                 int rows_total)
{
    __shared__ __half a_s[128 * A_STRIDE];
    __shared__ __half w_s[64 * W_STRIDE];

    const int tid = threadIdx.x;

    if (blockIdx.x < META_BLOCKS) {
        // ------------------------- META PATH -------------------------------
        if (blockIdx.x == 0 && tid < 16) {
            uint2 z; z.x = 0u; z.y = 0u;
            reinterpret_cast<uint2*>(pf)[(size_t)ZROW * 16 + tid] = z;
        }
        const int warp = tid >> 5;
        const int lane = tid & 31;
        #pragma unroll
        for (int it = 0; it < META_ROWS_PER_BLOCK / 16; it++) {
            const int rowA = blockIdx.x * META_ROWS_PER_BLOCK + it * 16 + warp * 2;
            if (rowA >= rows_total) break;
            const int row  = rowA + (lane >> 4);
            const int base = (row >> LOG2_K) << LOG2_K;

            const int   idx = n_idxs[rowA * 16 + lane];
            const int   v   = nvalid[rowA * 16 + lane];
            const float vf  = (float)v;
            const float* rp = nrel + (size_t)rowA * 48 + lane * 3;
            float r0 = rp[0] * vf, r1 = rp[1] * vf, r2 = rp[2] * vf, cnt = vf;

            eidx[rowA * 16 + lane] = v ? (base + idx) : ZROW;

            #pragma unroll
            for (int m = 1; m < 16; m <<= 1) {
                r0  += __shfl_xor_sync(0xffffffffu, r0,  m);
                r1  += __shfl_xor_sync(0xffffffffu, r1,  m);
                r2  += __shfl_xor_sync(0xffffffffu, r2,  m);
                cnt += __shfl_xor_sync(0xffffffffu, cnt, m);
            }
            if ((lane & 15) == 0) {
                const float inv = (cnt > 0.0f) ? (1.0f / cnt) : 0.0f;
                meta[row] = make_float4(r0, r1, r2, inv);
            }
        }
        return;
    }

    // --------------------------- PROJ PATH ---------------------------------
    const int pb = blockIdx.x - META_BLOCKS;

    for (int i = tid; i < 64 * 64; i += 256) {
        int o = i >> 6, k = i & 63;
        w_s[o * W_STRIDE + k] = __float2half(W[o * 67 + k]);
    }
    {
        const float4* fg = reinterpret_cast<const float4*>(feats)
                           + (size_t)pb * (128 * 16);
        const int row = tid >> 1;
        const int hs  = tid & 1;
        #pragma unroll
        for (int i = 0; i < 8; i++) {
            float4 v = fg[row * 16 + hs * 8 + i];
            __half2* dst = reinterpret_cast<__half2*>(
                a_s + row * A_STRIDE + hs * 32 + i * 4);
            dst[0] = __floats2half2_rn(v.x, v.y);
            dst[1] = __floats2half2_rn(v.z, v.w);
        }
    }
    __syncthreads();

    const int warp = tid >> 5;
    const int lane = tid & 31;
    const int g    = lane >> 2;
    const int t4   = lane & 3;

    float d[8][4];
    #pragma unroll
    for (int nt = 0; nt < 8; nt++)
        d[nt][0] = d[nt][1] = d[nt][2] = d[nt][3] = 0.0f;

    const uint32_t a_base = smem_u32(a_s)
        + ((warp * 16 + (lane & 15)) * A_STRIDE + (lane >> 4) * 8) * 2;
    const __half* wrow = w_s + g * W_STRIDE + t4 * 2;

    #pragma unroll
    for (int kt = 0; kt < 4; kt++) {
        uint32_t a0, a1, a2, a3;
        asm volatile(
            "ldmatrix.sync.aligned.m8n8.x4.shared.b16 {%0,%1,%2,%3}, [%4];"
            : "=r"(a0), "=r"(a1), "=r"(a2), "=r"(a3)
            : "r"(a_base + kt * 32));
        #pragma unroll
        for (int nt = 0; nt < 8; nt++) {
            const __half* wp = wrow + nt * 8 * W_STRIDE + kt * 16;
            const uint32_t b0 = *reinterpret_cast<const uint32_t*>(wp);
            const uint32_t b1 = *reinterpret_cast<const uint32_t*>(wp + 8);
            asm volatile(
                "mma.sync.aligned.m16n8k16.row.col.f32.f16.f16.f32 "
                "{%0,%1,%2,%3}, {%4,%5,%6,%7}, {%8,%9}, {%0,%1,%2,%3};"
                : "+f"(d[nt][0]), "+f"(d[nt][1]), "+f"(d[nt][2]), "+f"(d[nt][3])
                : "r"(a0), "r"(a1), "r"(a2), "r"(a3), "r"(b0), "r"(b1));
        }
    }

    const size_t row0 = (size_t)pb * 128 + warp * 16 + g;
    #pragma unroll
    for (int nt = 0; nt < 8; nt++) {
        const int col = nt * 8 + t4 * 2;
        *reinterpret_cast<__half2*>(pf + row0 * 64 + col)
            = __floats2half2_rn(d[nt][0], d[nt][1]);
        *reinterpret_cast<__half2*>(pf + (row0 + 8) * 64 + col)
            = __floats2half2_rn(d[nt][2], d[nt][3]);
    }
}

// ---------------------------------------------------------------------------
// Kernel 2: gather-sum. 8 lanes/row (lane owns 8 channels = uint4 of fp16),
// 4 rows/warp; 16 unconditional LDG.128 per row from precomputed indices.
// ---------------------------------------------------------------------------
#define THREADS 256
#define ROWS_PER_BLOCK 32   // 8 warps * 4 rows

__global__ __launch_bounds__(THREADS)
void gather_kernel(const __half* __restrict__ pf,
                   const int*    __restrict__ eidx,
                   const float4* __restrict__ meta,
                   const float*  __restrict__ W,     // [64][67]
                   const float*  __restrict__ bias,
                   float*        __restrict__ out,
                   int rows_total)
{
    __shared__ float wr_s[3 * 64];
    __shared__ float b_s[64];

    const int tid = threadIdx.x;
    for (int i = tid; i < 192; i += THREADS) {
        int jc = i >> 6, o = i & 63;
        wr_s[i] = W[o * 67 + 64 + jc];
    }
    if (tid < 64) b_s[tid] = bias[tid];
    __syncthreads();

    const int warp = tid >> 5;
    const int lane = tid & 31;
    const int q    = lane >> 3;   // row within warp (0..3)
    const int t    = lane & 7;    // channel octet id (channels 8t..8t+7)

    const float4* wr4 = reinterpret_cast<const float4*>(wr_s);
    const float4 w0a = wr4[0 * 16 + t * 2], w0b = wr4[0 * 16 + t * 2 + 1];
    const float4 w1a = wr4[1 * 16 + t * 2], w1b = wr4[1 * 16 + t * 2 + 1];
    const float4 w2a = wr4[2 * 16 + t * 2], w2b = wr4[2 * 16 + t * 2 + 1];
    const float4 bga = reinterpret_cast<const float4*>(b_s)[t * 2];
    const float4 bgb = reinterpret_cast<const float4*>(b_s)[t * 2 + 1];

    const uint4* pg = reinterpret_cast<const uint4*>(pf);

    const int row = blockIdx.x * ROWS_PER_BLOCK + warp * 4 + q;
    if (row >= rows_total) return;

    const int4* ep = reinterpret_cast<const int4*>(eidx + row * 16);
    const int4 ea = ep[0], eb = ep[1], ec = ep[2], ed = ep[3];
    const float4 mt = meta[row];

    const uint4 h0  = pg[(size_t)ea.x * 8 + t];
    const uint4 h1  = pg[(size_t)ea.y * 8 + t];
    const uint4 h2  = pg[(size_t)ea.z * 8 + t];
    const uint4 h3  = pg[(size_t)ea.w * 8 + t];
    const uint4 h4  = pg[(size_t)eb.x * 8 + t];
    const uint4 h5  = pg[(size_t)eb.y * 8 + t];
    const uint4 h6  = pg[(size_t)eb.z * 8 + t];
    const uint4 h7  = pg[(size_t)eb.w * 8 + t];
    const uint4 h8  = pg[(size_t)ec.x * 8 + t];
    const uint4 h9  = pg[(size_t)ec.y * 8 + t];
    const uint4 h10 = pg[(size_t)ec.z * 8 + t];
    const uint4 h11 = pg[(size_t)ec.w * 8 + t];
    const uint4 h12 = pg[(size_t)ed.x * 8 + t];
    const uint4 h13 = pg[(size_t)ed.y * 8 + t];
    const uint4 h14 = pg[(size_t)ed.z * 8 + t];
    const uint4 h15 = pg[(size_t)ed.w * 8 + t];

    float a0 = 0.f, a1 = 0.f, a2 = 0.f, a3 = 0.f;
    float a4 = 0.f, a5 = 0.f, a6 = 0.f, a7 = 0.f;
    #define ACCUM(H) do {                                                      \
        const float2 f0 = __half22float2(*reinterpret_cast<const __half2*>(&(H).x)); \
        const float2 f1 = __half22float2(*reinterpret_cast<const __half2*>(&(H).y)); \
        const float2 f2 = __half22float2(*reinterpret_cast<const __half2*>(&(H).z)); \
        const float2 f3 = __half22float2(*reinterpret_cast<const __half2*>(&(H).w)); \
        a0 += f0.x; a1 += f0.y; a2 += f1.x; a3 += f1.y;                        \
        a4 += f2.x; a5 += f2.y; a6 += f3.x; a7 += f3.y;                        \
    } while (0)
    ACCUM(h0);  ACCUM(h1);  ACCUM(h2);  ACCUM(h3);
    ACCUM(h4);  ACCUM(h5);  ACCUM(h6);  ACCUM(h7);
    ACCUM(h8);  ACCUM(h9);  ACCUM(h10); ACCUM(h11);
    ACCUM(h12); ACCUM(h13); ACCUM(h14); ACCUM(h15);
    #undef ACCUM

    a0 = fmaf(mt.x, w0a.x, a0); a1 = fmaf(mt.x, w0a.y, a1);
    a2 = fmaf(mt.x, w0a.z, a2); a3 = fmaf(mt.x, w0a.w, a3);
    a4 = fmaf(mt.x, w0b.x, a4); a5 = fmaf(mt.x, w0b.y, a5);
    a6 = fmaf(mt.x, w0b.z, a6); a7 = fmaf(mt.x, w0b.w, a7);
    a0 = fmaf(mt.y, w1a.x, a0); a1 = fmaf(mt.y, w1a.y, a1);
    a2 = fmaf(mt.y, w1a.z, a2); a3 = fmaf(mt.y, w1a.w, a3);
    a4 = fmaf(mt.y, w1b.x, a4); a5 = fmaf(mt.y, w1b.y, a5);
    a6 = fmaf(mt.y, w1b.z, a6); a7 = fmaf(mt.y, w1b.w, a7);
    a0 = fmaf(mt.z, w2a.x, a0); a1 = fmaf(mt.z, w2a.y, a1);
    a2 = fmaf(mt.z, w2a.z, a2); a3 = fmaf(mt.z, w2a.w, a3);
    a4 = fmaf(mt.z, w2b.x, a4); a5 = fmaf(mt.z, w2b.y, a5);
    a6 = fmaf(mt.z, w2b.z, a6); a7 = fmaf(mt.z, w2b.w, a7);

    float4 resA, resB;
    resA.x = fmaxf(fmaf(a0, mt.w, bga.x), 0.0f);
    resA.y = fmaxf(fmaf(a1, mt.w, bga.y), 0.0f);
    resA.z = fmaxf(fmaf(a2, mt.w, bga.z), 0.0f);
    resA.w = fmaxf(fmaf(a3, mt.w, bga.w), 0.0f);
    resB.x = fmaxf(fmaf(a4, mt.w, bgb.x), 0.0f);
    resB.y = fmaxf(fmaf(a5, mt.w, bgb.y), 0.0f);
    resB.z = fmaxf(fmaf(a6, mt.w, bgb.z), 0.0f);
    resB.w = fmaxf(fmaf(a7, mt.w, bgb.w), 0.0f);

    float4* op = reinterpret_cast<float4*>(out) + (size_t)row * 16;
    op[t * 2]     = resA;
    op[t * 2 + 1] = resB;
}

extern "C" void kernel_launch(void* const* d_in, const int* in_sizes, int n_in,
                              void* d_out, int out_size)
{
    // metadata order: keys, points, feats, n_idxs, neighbor_rel,
    //                 neighbor_valid, W, b
    const float* feats  = (const float*)d_in[2];
    const int*   n_idxs = (const int*)  d_in[3];
    const float* nrel   = (const float*)d_in[4];
    const int*   nvalid = (const int*)  d_in[5];
    const float* W      = (const float*)d_in[6];
    const float* bias   = (const float*)d_in[7];
    float*       out    = (float*)d_out;

    const int rows_total = out_size / 64;   // 131072

    __half* pf   = nullptr;
    int*    eidx = nullptr;
    float4* meta = nullptr;
    cudaGetSymbolAddress((void**)&pf,   g_pf);
    cudaGetSymbolAddress((void**)&eidx, g_eidx);
    cudaGetSymbolAddress((void**)&meta, g_meta);

    prep_kernel<<<META_BLOCKS + PROJ_BLOCKS, 256>>>(
        feats, W, n_idxs, nvalid, nrel, pf, eidx, meta, rows_total);

    const int grid = (rows_total + ROWS_PER_BLOCK - 1) / ROWS_PER_BLOCK;
    gather_kernel<<<grid, THREADS>>>(pf, eidx, meta, W, bias, out, rows_total);
}

// round 8
// speedup vs baseline: 1.0552x; 1.0552x over previous
#include <cuda_runtime.h>
#include <cuda_fp16.h>
#include <cstdint>

// GraphConv, 3-kernel pipeline (separate launches; separate register budgets):
//  K0 meta:  eidx[row][16] = valid ? batch_base+idx : ZROW ; meta[row]=(r0,r1,r2,inv)
//  K1 proj:  pf = fp16( feats @ Wf^T ) via HMMA m16n8k16 (fp32 accum)
//  K2 gather: out = relu( inv*( sum pf[eidx_n] + srel.W_rel ) + b )
// Shapes fixed: B=8, P=K=16384, N=16, IN=64, REL=3, OUT=64.

#define LOG2_K 14
#define ROWS_TOTAL (8 * 16384)
#define ZROW ROWS_TOTAL

__device__ __align__(16) __half g_pf[((size_t)ROWS_TOTAL + 1) * 64];
__device__ __align__(16) int    g_eidx[(size_t)ROWS_TOTAL * 16];
__device__ __align__(16) float4 g_meta[ROWS_TOTAL];

__device__ __forceinline__ uint32_t smem_u32(const void* p) {
    uint32_t a;
    asm("{ .reg .u64 t; cvta.to.shared.u64 t, %1; cvt.u32.u64 %0, t; }"
        : "=r"(a) : "l"(p));
    return a;
}

// ---------------------------------------------------------------------------
// Kernel 0: per-row metadata. Warp handles 2 row-pairs (4 rows) per call,
// loads for both pairs issued before the reductions (MLP x2).
// ---------------------------------------------------------------------------
__global__ __launch_bounds__(256)
void meta_kernel(const int*   __restrict__ n_idxs,
                 const int*   __restrict__ nvalid,
                 const float* __restrict__ nrel,
                 int*         __restrict__ eidx,
                 float4*      __restrict__ meta,
                 __half*      __restrict__ pf,
                 int rows_total)
{
    const int tid  = threadIdx.x;
    if (blockIdx.x == 0 && tid < 16) {   // zero the sentinel pf row
        uint2 z; z.x = 0u; z.y = 0u;
        reinterpret_cast<uint2*>(pf)[(size_t)ZROW * 16 + tid] = z;
    }

    const int warp = tid >> 5;
    const int lane = tid & 31;
    // warp covers rows [rowA, rowA+4): pair0 = rowA, pair1 = rowA+2
    const int rowA = blockIdx.x * 32 + warp * 4;
    if (rowA >= rows_total) return;

    // ---- issue all loads for both pairs up front ----
    const int   idxA = n_idxs[rowA * 16 + lane];
    const int   idxB = n_idxs[(rowA + 2) * 16 + lane];
    const int   vA   = nvalid[rowA * 16 + lane];
    const int   vB   = nvalid[(rowA + 2) * 16 + lane];
    const float* rpA = nrel + (size_t)rowA * 48 + lane * 3;
    const float* rpB = nrel + (size_t)(rowA + 2) * 48 + lane * 3;
    const float ra0 = rpA[0], ra1 = rpA[1], ra2 = rpA[2];
    const float rb0 = rpB[0], rb1 = rpB[1], rb2 = rpB[2];

    const int rowSelf = rowA + (lane >> 4);
    const int base    = (rowSelf >> LOG2_K) << LOG2_K;   // same for all 4 rows
                                                         // (rows never straddle
                                                         //  a 16384 boundary:
                                                         //  rowA % 4 == 0)
    eidx[rowA * 16 + lane]       = vA ? (base + idxA) : ZROW;
    eidx[(rowA + 2) * 16 + lane] = vB ? (base + idxB) : ZROW;

    const float vfA = (float)vA, vfB = (float)vB;
    float a0 = ra0 * vfA, a1 = ra1 * vfA, a2 = ra2 * vfA, ca = vfA;
    float b0 = rb0 * vfB, b1 = rb1 * vfB, b2 = rb2 * vfB, cb = vfB;

    #pragma unroll
    for (int m = 1; m < 16; m <<= 1) {
        a0 += __shfl_xor_sync(0xffffffffu, a0, m);
        a1 += __shfl_xor_sync(0xffffffffu, a1, m);
        a2 += __shfl_xor_sync(0xffffffffu, a2, m);
        ca += __shfl_xor_sync(0xffffffffu, ca, m);
        b0 += __shfl_xor_sync(0xffffffffu, b0, m);
        b1 += __shfl_xor_sync(0xffffffffu, b1, m);
        b2 += __shfl_xor_sync(0xffffffffu, b2, m);
        cb += __shfl_xor_sync(0xffffffffu, cb, m);
    }
    if ((lane & 15) == 0) {
        const float invA = (ca > 0.0f) ? (1.0f / ca) : 0.0f;
        const float invB = (cb > 0.0f) ? (1.0f / cb) : 0.0f;
        meta[rowSelf]     = make_float4(a0, a1, a2, invA);
        meta[rowSelf + 2] = make_float4(b0, b1, b2, invB);
    }
}

// ---------------------------------------------------------------------------
// Kernel 1: pf = feats @ Wf^T via HMMA m16n8k16 (fp16 in, fp32 acc).
// Block = 256 thr (8 warps), tile 128 rows x 64 outs; warp = 16 rows.
// ---------------------------------------------------------------------------
#define A_STRIDE 72
#define W_STRIDE 66

__global__ __launch_bounds__(256)
void proj_kernel(const float* __restrict__ feats,
                 const float* __restrict__ W,     // [64][67]
                 __half*      __restrict__ pf)
{
    __shared__ __half a_s[128 * A_STRIDE];
    __shared__ __half w_s[64 * W_STRIDE];

    const int tid = threadIdx.x;

    for (int i = tid; i < 64 * 64; i += 256) {
        int o = i >> 6, k = i & 63;
        w_s[o * W_STRIDE + k] = __float2half(W[o * 67 + k]);
    }
    {
        const float4* fg = reinterpret_cast<const float4*>(feats)
                           + (size_t)blockIdx.x * (128 * 16);
        const int row = tid >> 1;
        const int hs  = tid & 1;
        #pragma unroll
        for (int i = 0; i < 8; i++) {
            float4 v = fg[row * 16 + hs * 8 + i];
            __half2* dst = reinterpret_cast<__half2*>(
                a_s + row * A_STRIDE + hs * 32 + i * 4);
            dst[0] = __floats2half2_rn(v.x, v.y);
            dst[1] = __floats2half2_rn(v.z, v.w);
        }
    }
    __syncthreads();

    const int warp = tid >> 5;
    const int lane = tid & 31;
    const int g    = lane >> 2;
    const int t4   = lane & 3;

    float d[8][4];
    #pragma unroll
    for (int nt = 0; nt < 8; nt++)
        d[nt][0] = d[nt][1] = d[nt][2] = d[nt][3] = 0.0f;

    const uint32_t a_base = smem_u32(a_s)
        + ((warp * 16 + (lane & 15)) * A_STRIDE + (lane >> 4) * 8) * 2;
    const __half* wrow = w_s + g * W_STRIDE + t4 * 2;

    #pragma unroll
    for (int kt = 0; kt < 4; kt++) {
        uint32_t a0, a1, a2, a3;
        asm volatile(
            "ldmatrix.sync.aligned.m8n8.x4.shared.b16 {%0,%1,%2,%3}, [%4];"
            : "=r"(a0), "=r"(a1), "=r"(a2), "=r"(a3)
            : "r"(a_base + kt * 32));
        #pragma unroll
        for (int nt = 0; nt < 8; nt++) {
            const __half* wp = wrow + nt * 8 * W_STRIDE + kt * 16;
            const uint32_t b0 = *reinterpret_cast<const uint32_t*>(wp);
            const uint32_t b1 = *reinterpret_cast<const uint32_t*>(wp + 8);
            asm volatile(
                "mma.sync.aligned.m16n8k16.row.col.f32.f16.f16.f32 "
                "{%0,%1,%2,%3}, {%4,%5,%6,%7}, {%8,%9}, {%0,%1,%2,%3};"
                : "+f"(d[nt][0]), "+f"(d[nt][1]), "+f"(d[nt][2]), "+f"(d[nt][3])
                : "r"(a0), "r"(a1), "r"(a2), "r"(a3), "r"(b0), "r"(b1));
        }
    }

    const size_t row0 = (size_t)blockIdx.x * 128 + warp * 16 + g;
    #pragma unroll
    for (int nt = 0; nt < 8; nt++) {
        const int col = nt * 8 + t4 * 2;
        *reinterpret_cast<__half2*>(pf + row0 * 64 + col)
            = __floats2half2_rn(d[nt][0], d[nt][1]);
        *reinterpret_cast<__half2*>(pf + (row0 + 8) * 64 + col)
            = __floats2half2_rn(d[nt][2], d[nt][3]);
    }
}

// ---------------------------------------------------------------------------
// Kernel 2: gather-sum. 8 lanes/row (lane owns 8 channels = uint4 of fp16),
// 4 rows/warp; 16 unconditional LDG.128 per row from precomputed indices.
// ---------------------------------------------------------------------------
#define THREADS 256
#define ROWS_PER_BLOCK 32   // 8 warps * 4 rows

__global__ __launch_bounds__(THREADS)
void gather_kernel(const __half* __restrict__ pf,
                   const int*    __restrict__ eidx,
                   const float4* __restrict__ meta,
                   const float*  __restrict__ W,     // [64][67]
                   const float*  __restrict__ bias,
                   float*        __restrict__ out,
                   int rows_total)
{
    __shared__ float wr_s[3 * 64];
    __shared__ float b_s[64];

    const int tid = threadIdx.x;
    for (int i = tid; i < 192; i += THREADS) {
        int jc = i >> 6, o = i & 63;
        wr_s[i] = W[o * 67 + 64 + jc];
    }
    if (tid < 64) b_s[tid] = bias[tid];
    __syncthreads();

    const int warp = tid >> 5;
    const int lane = tid & 31;
    const int q    = lane >> 3;   // row within warp (0..3)
    const int t    = lane & 7;    // channel octet id (channels 8t..8t+7)

    const float4* wr4 = reinterpret_cast<const float4*>(wr_s);
    const float4 w0a = wr4[0 * 16 + t * 2], w0b = wr4[0 * 16 + t * 2 + 1];
    const float4 w1a = wr4[1 * 16 + t * 2], w1b = wr4[1 * 16 + t * 2 + 1];
    const float4 w2a = wr4[2 * 16 + t * 2], w2b = wr4[2 * 16 + t * 2 + 1];
    const float4 bga = reinterpret_cast<const float4*>(b_s)[t * 2];
    const float4 bgb = reinterpret_cast<const float4*>(b_s)[t * 2 + 1];

    const uint4* pg = reinterpret_cast<const uint4*>(pf);

    const int row = blockIdx.x * ROWS_PER_BLOCK + warp * 4 + q;
    if (row >= rows_total) return;

    const int4* ep = reinterpret_cast<const int4*>(eidx + row * 16);
    const int4 ea = ep[0], eb = ep[1], ec = ep[2], ed = ep[3];
    const float4 mt = meta[row];

    const uint4 h0  = pg[(size_t)ea.x * 8 + t];
    const uint4 h1  = pg[(size_t)ea.y * 8 + t];
    const uint4 h2  = pg[(size_t)ea.z * 8 + t];
    const uint4 h3  = pg[(size_t)ea.w * 8 + t];
    const uint4 h4  = pg[(size_t)eb.x * 8 + t];
    const uint4 h5  = pg[(size_t)eb.y * 8 + t];
    const uint4 h6  = pg[(size_t)eb.z * 8 + t];
    const uint4 h7  = pg[(size_t)eb.w * 8 + t];
    const uint4 h8  = pg[(size_t)ec.x * 8 + t];
    const uint4 h9  = pg[(size_t)ec.y * 8 + t];
    const uint4 h10 = pg[(size_t)ec.z * 8 + t];
    const uint4 h11 = pg[(size_t)ec.w * 8 + t];
    const uint4 h12 = pg[(size_t)ed.x * 8 + t];
    const uint4 h13 = pg[(size_t)ed.y * 8 + t];
    const uint4 h14 = pg[(size_t)ed.z * 8 + t];
    const uint4 h15 = pg[(size_t)ed.w * 8 + t];

    float a0 = 0.f, a1 = 0.f, a2 = 0.f, a3 = 0.f;
    float a4 = 0.f, a5 = 0.f, a6 = 0.f, a7 = 0.f;
    #define ACCUM(H) do {                                                      \
        const float2 f0 = __half22float2(*reinterpret_cast<const __half2*>(&(H).x)); \
        const float2 f1 = __half22float2(*reinterpret_cast<const __half2*>(&(H).y)); \
        const float2 f2 = __half22float2(*reinterpret_cast<const __half2*>(&(H).z)); \
        const float2 f3 = __half22float2(*reinterpret_cast<const __half2*>(&(H).w)); \
        a0 += f0.x; a1 += f0.y; a2 += f1.x; a3 += f1.y;                        \
        a4 += f2.x; a5 += f2.y; a6 += f3.x; a7 += f3.y;                        \
    } while (0)
    ACCUM(h0);  ACCUM(h1);  ACCUM(h2);  ACCUM(h3);
    ACCUM(h4);  ACCUM(h5);  ACCUM(h6);  ACCUM(h7);
    ACCUM(h8);  ACCUM(h9);  ACCUM(h10); ACCUM(h11);
    ACCUM(h12); ACCUM(h13); ACCUM(h14); ACCUM(h15);
    #undef ACCUM

    a0 = fmaf(mt.x, w0a.x, a0); a1 = fmaf(mt.x, w0a.y, a1);
    a2 = fmaf(mt.x, w0a.z, a2); a3 = fmaf(mt.x, w0a.w, a3);
    a4 = fmaf(mt.x, w0b.x, a4); a5 = fmaf(mt.x, w0b.y, a5);
    a6 = fmaf(mt.x, w0b.z, a6); a7 = fmaf(mt.x, w0b.w, a7);
    a0 = fmaf(mt.y, w1a.x, a0); a1 = fmaf(mt.y, w1a.y, a1);
    a2 = fmaf(mt.y, w1a.z, a2); a3 = fmaf(mt.y, w1a.w, a3);
    a4 = fmaf(mt.y, w1b.x, a4); a5 = fmaf(mt.y, w1b.y, a5);
    a6 = fmaf(mt.y, w1b.z, a6); a7 = fmaf(mt.y, w1b.w, a7);
    a0 = fmaf(mt.z, w2a.x, a0); a1 = fmaf(mt.z, w2a.y, a1);
    a2 = fmaf(mt.z, w2a.z, a2); a3 = fmaf(mt.z, w2a.w, a3);
    a4 = fmaf(mt.z, w2b.x, a4); a5 = fmaf(mt.z, w2b.y, a5);
    a6 = fmaf(mt.z, w2b.z, a6); a7 = fmaf(mt.z, w2b.w, a7);

    float4 resA, resB;
    resA.x = fmaxf(fmaf(a0, mt.w, bga.x), 0.0f);
    resA.y = fmaxf(fmaf(a1, mt.w, bga.y), 0.0f);
    resA.z = fmaxf(fmaf(a2, mt.w, bga.z), 0.0f);
    resA.w = fmaxf(fmaf(a3, mt.w, bga.w), 0.0f);
    resB.x = fmaxf(fmaf(a4, mt.w, bgb.x), 0.0f);
    resB.y = fmaxf(fmaf(a5, mt.w, bgb.y), 0.0f);
    resB.z = fmaxf(fmaf(a6, mt.w, bgb.z), 0.0f);
    resB.w = fmaxf(fmaf(a7, mt.w, bgb.w), 0.0f);

    float4* op = reinterpret_cast<float4*>(out) + (size_t)row * 16;
    op[t * 2]     = resA;
    op[t * 2 + 1] = resB;
}

extern "C" void kernel_launch(void* const* d_in, const int* in_sizes, int n_in,
                              void* d_out, int out_size)
{
    // metadata order: keys, points, feats, n_idxs, neighbor_rel,
    //                 neighbor_valid, W, b
    const float* feats  = (const float*)d_in[2];
    const int*   n_idxs = (const int*)  d_in[3];
    const float* nrel   = (const float*)d_in[4];
    const int*   nvalid = (const int*)  d_in[5];
    const float* W      = (const float*)d_in[6];
    const float* bias   = (const float*)d_in[7];
    float*       out    = (float*)d_out;

    const int rows_total = out_size / 64;   // 131072

    __half* pf   = nullptr;
    int*    eidx = nullptr;
    float4* meta = nullptr;
    cudaGetSymbolAddress((void**)&pf,   g_pf);
    cudaGetSymbolAddress((void**)&eidx, g_eidx);
    cudaGetSymbolAddress((void**)&meta, g_meta);

    meta_kernel<<<(rows_total + 31) / 32, 256>>>(n_idxs, nvalid, nrel,
                                                 eidx, meta, pf, rows_total);
    proj_kernel<<<rows_total / 128, 256>>>(feats, W, pf);

    const int grid = (rows_total + ROWS_PER_BLOCK - 1) / ROWS_PER_BLOCK;
    gather_kernel<<<grid, THREADS>>>(pf, eidx, meta, W, bias, out, rows_total);
}

// round 9
// speedup vs baseline: 1.1510x; 1.0908x over previous
#include <cuda_runtime.h>
#include <cuda_fp16.h>
#include <cstdint>

// GraphConv, 2-kernel pipeline:
//  K1 proj:   pf = fp16( feats @ Wf^T ) via HMMA m16n8k16 (fp32 accum)
//             (+ zero the sentinel row)
//  K2 gather: out = relu( inv*( sum_{n valid} pf[idx_n] + srel.W_rel ) + b )
//             metadata (idx/valid/rel) computed inline, off the load path.
// Shapes fixed: B=8, P=K=16384, N=16, IN=64, REL=3, OUT=64.

#define LOG2_K 14
#define ROWS_TOTAL (8 * 16384)
#define ZROW ROWS_TOTAL

__device__ __align__(16) __half g_pf[((size_t)ROWS_TOTAL + 1) * 64];

__device__ __forceinline__ uint32_t smem_u32(const void* p) {
    uint32_t a;
    asm("{ .reg .u64 t; cvta.to.shared.u64 t, %1; cvt.u32.u64 %0, t; }"
        : "=r"(a) : "l"(p));
    return a;
}

// ---------------------------------------------------------------------------
// Kernel 1: pf = feats @ Wf^T via HMMA (fp16 in, fp32 acc).
// Block = 256 thr (8 warps), tile 128 rows x 64 outs; warp = 16 rows.
// ---------------------------------------------------------------------------
#define A_STRIDE 72
#define W_STRIDE 66

__global__ __launch_bounds__(256)
void proj_kernel(const float* __restrict__ feats,
                 const float* __restrict__ W,     // [64][67]
                 __half*      __restrict__ pf)
{
    __shared__ __half a_s[128 * A_STRIDE];
    __shared__ __half w_s[64 * W_STRIDE];

    const int tid = threadIdx.x;

    if (blockIdx.x == 0 && tid < 16) {   // zero the sentinel pf row
        uint2 z; z.x = 0u; z.y = 0u;
        reinterpret_cast<uint2*>(pf)[(size_t)ZROW * 16 + tid] = z;
    }

    for (int i = tid; i < 64 * 64; i += 256) {
        int o = i >> 6, k = i & 63;
        w_s[o * W_STRIDE + k] = __float2half(W[o * 67 + k]);
    }
    {
        const float4* fg = reinterpret_cast<const float4*>(feats)
                           + (size_t)blockIdx.x * (128 * 16);
        const int row = tid >> 1;
        const int hs  = tid & 1;
        #pragma unroll
        for (int i = 0; i < 8; i++) {
            float4 v = fg[row * 16 + hs * 8 + i];
            __half2* dst = reinterpret_cast<__half2*>(
                a_s + row * A_STRIDE + hs * 32 + i * 4);
            dst[0] = __floats2half2_rn(v.x, v.y);
            dst[1] = __floats2half2_rn(v.z, v.w);
        }
    }
    __syncthreads();

    const int warp = tid >> 5;
    const int lane = tid & 31;
    const int g    = lane >> 2;
    const int t4   = lane & 3;

    float d[8][4];
    #pragma unroll
    for (int nt = 0; nt < 8; nt++)
        d[nt][0] = d[nt][1] = d[nt][2] = d[nt][3] = 0.0f;

    const uint32_t a_base = smem_u32(a_s)
        + ((warp * 16 + (lane & 15)) * A_STRIDE + (lane >> 4) * 8) * 2;
    const __half* wrow = w_s + g * W_STRIDE + t4 * 2;

    #pragma unroll
    for (int kt = 0; kt < 4; kt++) {
        uint32_t a0, a1, a2, a3;
        asm volatile(
            "ldmatrix.sync.aligned.m8n8.x4.shared.b16 {%0,%1,%2,%3}, [%4];"
            : "=r"(a0), "=r"(a1), "=r"(a2), "=r"(a3)
            : "r"(a_base + kt * 32));
        #pragma unroll
        for (int nt = 0; nt < 8; nt++) {
            const __half* wp = wrow + nt * 8 * W_STRIDE + kt * 16;
            const uint32_t b0 = *reinterpret_cast<const uint32_t*>(wp);
            const uint32_t b1 = *reinterpret_cast<const uint32_t*>(wp + 8);
            asm volatile(
                "mma.sync.aligned.m16n8k16.row.col.f32.f16.f16.f32 "
                "{%0,%1,%2,%3}, {%4,%5,%6,%7}, {%8,%9}, {%0,%1,%2,%3};"
                : "+f"(d[nt][0]), "+f"(d[nt][1]), "+f"(d[nt][2]), "+f"(d[nt][3])
                : "r"(a0), "r"(a1), "r"(a2), "r"(a3), "r"(b0), "r"(b1));
        }
    }

    const size_t row0 = (size_t)blockIdx.x * 128 + warp * 16 + g;
    #pragma unroll
    for (int nt = 0; nt < 8; nt++) {
        const int col = nt * 8 + t4 * 2;
        *reinterpret_cast<__half2*>(pf + row0 * 64 + col)
            = __floats2half2_rn(d[nt][0], d[nt][1]);
        *reinterpret_cast<__half2*>(pf + (row0 + 8) * 64 + col)
            = __floats2half2_rn(d[nt][2], d[nt][3]);
    }
}

// ---------------------------------------------------------------------------
// Kernel 2: gather-sum with inline metadata.
// 8 lanes/row (lane owns 8 channels = uint4 of fp16), 4 rows/warp.
// Order: idx/valid/rel loads -> eidx SELs -> 16 LDG.128 gathers ->
//        rel/cnt shuffle-reduce (hidden under gather latency) -> accumulate.
// ---------------------------------------------------------------------------
#define THREADS 256
#define ROWS_PER_BLOCK 32   // 8 warps * 4 rows

#define EIDX(V, I) (((V) != 0) ? (base + (I)) : ZROW)

__global__ __launch_bounds__(THREADS)
void gather_kernel(const __half* __restrict__ pf,
                   const int*    __restrict__ n_idxs,
                   const int*    __restrict__ nvalid,
                   const float*  __restrict__ nrel,
                   const float*  __restrict__ W,     // [64][67]
                   const float*  __restrict__ bias,
                   float*        __restrict__ out,
                   int rows_total)
{
    __shared__ float wr_s[3 * 64];   // wr_s[jc*64+o] = W[o*67 + 64 + jc]
    __shared__ float b_s[64];

    const int tid = threadIdx.x;
    for (int i = tid; i < 192; i += THREADS) {
        int jc = i >> 6, o = i & 63;
        wr_s[i] = W[o * 67 + 64 + jc];
    }
    if (tid < 64) b_s[tid] = bias[tid];
    __syncthreads();

    const int warp = tid >> 5;
    const int lane = tid & 31;
    const int q    = lane >> 3;   // row within warp (0..3)
    const int t    = lane & 7;    // channel octet id (channels 8t..8t+7)

    const int row = blockIdx.x * ROWS_PER_BLOCK + warp * 4 + q;
    if (row >= rows_total) return;
    const int base = (row >> LOG2_K) << LOG2_K;

    // ---- metadata loads (broadcast within 8-lane group / small per-lane) ----
    const int4* ip = reinterpret_cast<const int4*>(n_idxs + row * 16);
    const int4* vp = reinterpret_cast<const int4*>(nvalid + row * 16);
    const int4 ia = ip[0], ib = ip[1], ic = ip[2], id = ip[3];
    const int4 va = vp[0], vb = vp[1], vc = vp[2], vd = vp[3];

    // lane t handles rel of neighbors 2t, 2t+1: floats [6t, 6t+6)
    const float2* rp2 = reinterpret_cast<const float2*>(nrel + (size_t)row * 48);
    const float2 ra = rp2[3 * t + 0];
    const float2 rb = rp2[3 * t + 1];
    const float2 rc = rp2[3 * t + 2];
    const int2 vpair = *reinterpret_cast<const int2*>(nvalid + row * 16 + 2 * t);

    // ---- effective pf rows (pure ALU) ----
    const int e0  = EIDX(va.x, ia.x), e1  = EIDX(va.y, ia.y);
    const int e2  = EIDX(va.z, ia.z), e3  = EIDX(va.w, ia.w);
    const int e4  = EIDX(vb.x, ib.x), e5  = EIDX(vb.y, ib.y);
    const int e6  = EIDX(vb.z, ib.z), e7  = EIDX(vb.w, ib.w);
    const int e8  = EIDX(vc.x, ic.x), e9  = EIDX(vc.y, ic.y);
    const int e10 = EIDX(vc.z, ic.z), e11 = EIDX(vc.w, ic.w);
    const int e12 = EIDX(vd.x, id.x), e13 = EIDX(vd.y, id.y);
    const int e14 = EIDX(vd.z, id.z), e15 = EIDX(vd.w, id.w);

    // ---- 16 unconditional gathers (full MLP) ----
    const uint4* pg = reinterpret_cast<const uint4*>(pf);
    const uint4 h0  = pg[(size_t)e0  * 8 + t];
    const uint4 h1  = pg[(size_t)e1  * 8 + t];
    const uint4 h2  = pg[(size_t)e2  * 8 + t];
    const uint4 h3  = pg[(size_t)e3  * 8 + t];
    const uint4 h4  = pg[(size_t)e4  * 8 + t];
    const uint4 h5  = pg[(size_t)e5  * 8 + t];
    const uint4 h6  = pg[(size_t)e6  * 8 + t];
    const uint4 h7  = pg[(size_t)e7  * 8 + t];
    const uint4 h8  = pg[(size_t)e8  * 8 + t];
    const uint4 h9  = pg[(size_t)e9  * 8 + t];
    const uint4 h10 = pg[(size_t)e10 * 8 + t];
    const uint4 h11 = pg[(size_t)e11 * 8 + t];
    const uint4 h12 = pg[(size_t)e12 * 8 + t];
    const uint4 h13 = pg[(size_t)e13 * 8 + t];
    const uint4 h14 = pg[(size_t)e14 * 8 + t];
    const uint4 h15 = pg[(size_t)e15 * 8 + t];

    // ---- rel/cnt reduction (executes under gather latency) ----
    // neighbor 2t rel = (ra.x, ra.y, rb.x); neighbor 2t+1 rel = (rb.y, rc.x, rc.y)
    const float vfa = (float)vpair.x, vfb = (float)vpair.y;
    float r0  = ra.x * vfa + rb.y * vfb;
    float r1  = ra.y * vfa + rc.x * vfb;
    float r2  = rb.x * vfa + rc.y * vfb;
    float cnt = vfa + vfb;
    #pragma unroll
    for (int m = 1; m < 8; m <<= 1) {
        r0  += __shfl_xor_sync(0xffffffffu, r0,  m);
        r1  += __shfl_xor_sync(0xffffffffu, r1,  m);
        r2  += __shfl_xor_sync(0xffffffffu, r2,  m);
        cnt += __shfl_xor_sync(0xffffffffu, cnt, m);
    }
    const float inv = (cnt > 0.0f) ? (1.0f / cnt) : 0.0f;

    // ---- accumulate gathered rows ----
    float a0 = 0.f, a1 = 0.f, a2 = 0.f, a3 = 0.f;
    float a4 = 0.f, a5 = 0.f, a6 = 0.f, a7 = 0.f;
    #define ACCUM(H) do {                                                      \
        const float2 f0 = __half22float2(*reinterpret_cast<const __half2*>(&(H).x)); \
        const float2 f1 = __half22float2(*reinterpret_cast<const __half2*>(&(H).y)); \
        const float2 f2 = __half22float2(*reinterpret_cast<const __half2*>(&(H).z)); \
        const float2 f3 = __half22float2(*reinterpret_cast<const __half2*>(&(H).w)); \
        a0 += f0.x; a1 += f0.y; a2 += f1.x; a3 += f1.y;                        \
        a4 += f2.x; a5 += f2.y; a6 += f3.x; a7 += f3.y;                        \
    } while (0)
    ACCUM(h0);  ACCUM(h1);  ACCUM(h2);  ACCUM(h3);
    ACCUM(h4);  ACCUM(h5);  ACCUM(h6);  ACCUM(h7);
    ACCUM(h8);  ACCUM(h9);  ACCUM(h10); ACCUM(h11);
    ACCUM(h12); ACCUM(h13); ACCUM(h14); ACCUM(h15);
    #undef ACCUM

    // ---- rel-channel contribution + epilogue ----
    const float4* wr4 = reinterpret_cast<const float4*>(wr_s);
    const float4 w0a = wr4[0 * 16 + t * 2], w0b = wr4[0 * 16 + t * 2 + 1];
    const float4 w1a = wr4[1 * 16 + t * 2], w1b = wr4[1 * 16 + t * 2 + 1];
    const float4 w2a = wr4[2 * 16 + t * 2], w2b = wr4[2 * 16 + t * 2 + 1];
    const float4 bga = reinterpret_cast<const float4*>(b_s)[t * 2];
    const float4 bgb = reinterpret_cast<const float4*>(b_s)[t * 2 + 1];

    a0 = fmaf(r0, w0a.x, a0); a1 = fmaf(r0, w0a.y, a1);
    a2 = fmaf(r0, w0a.z, a2); a3 = fmaf(r0, w0a.w, a3);
    a4 = fmaf(r0, w0b.x, a4); a5 = fmaf(r0, w0b.y, a5);
    a6 = fmaf(r0, w0b.z, a6); a7 = fmaf(r0, w0b.w, a7);
    a0 = fmaf(r1, w1a.x, a0); a1 = fmaf(r1, w1a.y, a1);
    a2 = fmaf(r1, w1a.z, a2); a3 = fmaf(r1, w1a.w, a3);
    a4 = fmaf(r1, w1b.x, a4); a5 = fmaf(r1, w1b.y, a5);
    a6 = fmaf(r1, w1b.z, a6); a7 = fmaf(r1, w1b.w, a7);
    a0 = fmaf(r2, w2a.x, a0); a1 = fmaf(r2, w2a.y, a1);
    a2 = fmaf(r2, w2a.z, a2); a3 = fmaf(r2, w2a.w, a3);
    a4 = fmaf(r2, w2b.x, a4); a5 = fmaf(r2, w2b.y, a5);
    a6 = fmaf(r2, w2b.z, a6); a7 = fmaf(r2, w2b.w, a7);

    float4 resA, resB;
    resA.x = fmaxf(fmaf(a0, inv, bga.x), 0.0f);
    resA.y = fmaxf(fmaf(a1, inv, bga.y), 0.0f);
    resA.z = fmaxf(fmaf(a2, inv, bga.z), 0.0f);
    resA.w = fmaxf(fmaf(a3, inv, bga.w), 0.0f);
    resB.x = fmaxf(fmaf(a4, inv, bgb.x), 0.0f);
    resB.y = fmaxf(fmaf(a5, inv, bgb.y), 0.0f);
    resB.z = fmaxf(fmaf(a6, inv, bgb.z), 0.0f);
    resB.w = fmaxf(fmaf(a7, inv, bgb.w), 0.0f);

    float4* op = reinterpret_cast<float4*>(out) + (size_t)row * 16;
    op[t * 2]     = resA;
    op[t * 2 + 1] = resB;
}

extern "C" void kernel_launch(void* const* d_in, const int* in_sizes, int n_in,
                              void* d_out, int out_size)
{
    // metadata order: keys, points, feats, n_idxs, neighbor_rel,
    //                 neighbor_valid, W, b
    const float* feats  = (const float*)d_in[2];
    const int*   n_idxs = (const int*)  d_in[3];
    const float* nrel   = (const float*)d_in[4];
    const int*   nvalid = (const int*)  d_in[5];
    const float* W      = (const float*)d_in[6];
    const float* bias   = (const float*)d_in[7];
    float*       out    = (float*)d_out;

    const int rows_total = out_size / 64;   // 131072

    __half* pf = nullptr;
    cudaGetSymbolAddress((void**)&pf, g_pf);

    proj_kernel<<<rows_total / 128, 256>>>(feats, W, pf);

    const int grid = (rows_total + ROWS_PER_BLOCK - 1) / ROWS_PER_BLOCK;
    gather_kernel<<<grid, THREADS>>>(pf, n_idxs, nvalid, nrel,
                                     W, bias, out, rows_total);
}